// round 1
// baseline (speedup 1.0000x reference)
#include <cuda_runtime.h>
#include <cuda_bf16.h>
#include <stdint.h>

// Scatter-add F_st[e] * edge_vec[e] into out[edge_idx[e]], n_atoms x 3.
// Strategy: 16B-padded float4 accumulator in device-global scratch so every
// edge does ONE red.global.add.v4.f32 (instead of 3 scalar atomics), then a
// tiny copy kernel compacts [n,4] -> [n,3] into d_out.

#define MAX_ATOMS 100000

__device__ float4 g_acc[MAX_ATOMS];

__device__ __forceinline__ void red_add_v4(float4* p, float x, float y, float z) {
    asm volatile("red.global.add.v4.f32 [%0], {%1, %2, %3, %4};"
                 :: "l"(p), "f"(x), "f"(y), "f"(z), "f"(0.0f)
                 : "memory");
}

__global__ void zero_kernel(int n_atoms) {
    int i = blockIdx.x * blockDim.x + threadIdx.x;
    if (i < n_atoms) g_acc[i] = make_float4(0.f, 0.f, 0.f, 0.f);
}

// 4 edges per thread, all loads LDG.128.
__global__ void scatter_kernel(const float4* __restrict__ F4,
                               const float4* __restrict__ V4,
                               const int4*   __restrict__ I4,
                               int nq, int n_edges, int n_atoms) {
    int t = blockIdx.x * blockDim.x + threadIdx.x;
    if (t < nq) {
        float4 f  = F4[t];
        float4 a  = V4[3 * t + 0];
        float4 b  = V4[3 * t + 1];
        float4 c  = V4[3 * t + 2];
        int4   id = I4[t];

        // edge layout: e0=(a.x,a.y,a.z) e1=(a.w,b.x,b.y) e2=(b.z,b.w,c.x) e3=(c.y,c.z,c.w)
        if ((unsigned)id.x < (unsigned)n_atoms)
            red_add_v4(&g_acc[id.x], f.x * a.x, f.x * a.y, f.x * a.z);
        if ((unsigned)id.y < (unsigned)n_atoms)
            red_add_v4(&g_acc[id.y], f.y * a.w, f.y * b.x, f.y * b.y);
        if ((unsigned)id.z < (unsigned)n_atoms)
            red_add_v4(&g_acc[id.z], f.z * b.z, f.z * b.w, f.z * c.x);
        if ((unsigned)id.w < (unsigned)n_atoms)
            red_add_v4(&g_acc[id.w], f.w * c.y, f.w * c.z, f.w * c.w);
    } else if (t == nq) {
        // scalar tail (n_edges % 4 edges), handled by exactly one thread
        const float* F   = (const float*)F4;
        const float* V   = (const float*)V4;
        const int*   IDX = (const int*)I4;
        for (int e = 4 * nq; e < n_edges; e++) {
            float f = F[e];
            int   i = IDX[e];
            if ((unsigned)i < (unsigned)n_atoms)
                red_add_v4(&g_acc[i], f * V[3 * e + 0], f * V[3 * e + 1], f * V[3 * e + 2]);
        }
    }
}

__global__ void copy_kernel(float* __restrict__ out, int n_atoms) {
    int i = blockIdx.x * blockDim.x + threadIdx.x;
    if (i < n_atoms) {
        float4 v = g_acc[i];
        out[3 * i + 0] = v.x;
        out[3 * i + 1] = v.y;
        out[3 * i + 2] = v.z;
    }
}

extern "C" void kernel_launch(void* const* d_in, const int* in_sizes, int n_in,
                              void* d_out, int out_size) {
    const float4* F4 = (const float4*)d_in[0];   // F_st   [E,1] f32
    const float4* V4 = (const float4*)d_in[1];   // edge_vec [E,3] f32
    const int4*   I4 = (const int4*)d_in[2];     // edge_idx [E] i32
    float* out = (float*)d_out;                  // [n_atoms,3] f32

    int n_edges = in_sizes[0];
    int n_atoms = out_size / 3;
    if (n_atoms > MAX_ATOMS) n_atoms = MAX_ATOMS;

    int nq = n_edges / 4;

    const int TB = 256;
    zero_kernel<<<(n_atoms + TB - 1) / TB, TB>>>(n_atoms);
    // nq+1 threads: the extra thread handles the scalar tail
    scatter_kernel<<<(nq + 1 + TB - 1) / TB, TB>>>(F4, V4, I4, nq, n_edges, n_atoms);
    copy_kernel<<<(n_atoms + TB - 1) / TB, TB>>>(out, n_atoms);
}